// round 3
// baseline (speedup 1.0000x reference)
#include <cuda_runtime.h>

// BG_LSTM: B=512, T=512, H=256, input size 1.
// 16 clusters x 8 CTAs. Cluster owns 32 batches; CTA rank owns 32 hidden
// units (16 unit-pairs). W_hh slice resident in SMEM as f32x2 unit-pairs;
// h tile duplicated in SMEM so FFMA2 needs no splat MOVs. Cell state in
// registers; h exchanged via L2 with one release/acquire cluster barrier
// per step. 512 threads/CTA = 4 warps/SMSP.

#define BB 512
#define TT 512
#define HH 256
#define CLUSTER 8
#define NCTA 128
#define NTHREADS 512
#define UPC 32          // hidden units per CTA (16 pairs)
#define BPT 32          // batch tile per cluster

__device__ float g_h[2][HH][BB];   // [buf][unit][batch]

typedef unsigned long long u64;

__device__ __forceinline__ u64 pack2(float a, float b) {
    u64 r;
    asm("mov.b64 %0, {%1, %2};" : "=l"(r)
        : "r"(__float_as_uint(a)), "r"(__float_as_uint(b)));
    return r;
}
__device__ __forceinline__ void unpack2(u64 v, float &a, float &b) {
    unsigned int lo, hi;
    asm("mov.b64 {%0, %1}, %2;" : "=r"(lo), "=r"(hi) : "l"(v));
    a = __uint_as_float(lo); b = __uint_as_float(hi);
}
__device__ __forceinline__ void ffma2(u64 &acc, u64 a, u64 b) {
    asm("fma.rn.f32x2 %0, %1, %2, %3;" : "=l"(acc) : "l"(a), "l"(b), "l"(acc));
}
__device__ __forceinline__ void cluster_arrive_rel() {
    asm volatile("barrier.cluster.arrive.release.aligned;" ::: "memory");
}
__device__ __forceinline__ void cluster_wait_acq() {
    asm volatile("barrier.cluster.wait.acquire.aligned;" ::: "memory");
}
__device__ __forceinline__ float sigm(float x) {
    return __fdividef(1.0f, 1.0f + __expf(-x));
}
__device__ __forceinline__ float tanhe(float x) {
    return __fdividef(2.0f, 1.0f + __expf(-2.0f * x)) - 1.0f;
}

// SMEM: Ws[256*128] ++ hs_dup[256*64] ++ xs[32*65]
#define WS_FLOATS (HH * 128)          // 32768
#define HS_FLOATS (HH * 64)           // 16384 (duplicated pairs)
#define XS_FLOATS (32 * 65)           // 2080
extern __shared__ __align__(16) float smem[];

__global__ void __cluster_dims__(CLUSTER, 1, 1) __launch_bounds__(NTHREADS, 1)
lstm_kernel(const float* __restrict__ x,    const float* __restrict__ wih,
            const float* __restrict__ whh,  const float* __restrict__ bih,
            const float* __restrict__ bhh,  const float* __restrict__ wfc,
            const float* __restrict__ bfc,  float* __restrict__ out)
{
    float* Ws = smem;                       // [k][up*8 + g*2 + j]
    float* hs = smem + WS_FLOATS;           // [k][b*2 + {0,1}] duplicated
    float* xs = smem + WS_FLOATS + HS_FLOATS; // [b][65]

    const int t      = threadIdx.x;
    const int cta    = blockIdx.x;
    const int rank   = cta & (CLUSTER - 1);
    const int cl     = cta / CLUSTER;
    const int batch0 = cl * BPT;
    const int unit0  = rank * UPC;
    const int up     = t >> 5;    // 0..15 : unit-pair
    const int b      = t & 31;    // 0..31 : batch lane

    // ---- Stage W_hh slice: Ws[k*128 + (uu>>1)*8 + g*2 + (uu&1)] ----
    {
        const float4* w4 = (const float4*)whh;
        #pragma unroll
        for (int j = 0; j < 16; j++) {
            int idx   = t + j * NTHREADS;   // 0..8191 float4 granules
            int row_l = idx >> 6;           // 0..127  = uu*4 + g
            int k4    = idx & 63;
            int uu = row_l >> 2, g = row_l & 3;
            float4 w = __ldg(&w4[(g * HH + unit0 + uu) * (HH / 4) + k4]);
            int col = (uu >> 1) * 8 + g * 2 + (uu & 1);
            Ws[(k4 * 4 + 0) * 128 + col] = w.x;
            Ws[(k4 * 4 + 1) * 128 + col] = w.y;
            Ws[(k4 * 4 + 2) * 128 + col] = w.z;
            Ws[(k4 * 4 + 3) * 128 + col] = w.w;
        }
    }

    // ---- Per-thread gate params for my 2 units ----
    float wihr[4][2], biasr[4][2];
    #pragma unroll
    for (int g = 0; g < 4; g++)
        #pragma unroll
        for (int j = 0; j < 2; j++) {
            int r = g * HH + unit0 + 2 * up + j;
            wihr[g][j]  = __ldg(&wih[r]);
            biasr[g][j] = __ldg(&bih[r]) + __ldg(&bhh[r]);
        }

    // ---- Zero my h slice (initial h = 0) ----
    __stcg(&g_h[0][unit0 + 2 * up + 0][batch0 + b], 0.f);
    __stcg(&g_h[0][unit0 + 2 * up + 1][batch0 + b], 0.f);
    float c0 = 0.f, c1 = 0.f;

    __syncthreads();
    cluster_arrive_rel();
    cluster_wait_acq();

    int p = 0;
    for (int step = 0; step < TT; step++) {
        // ---- Stage h tile [256 units][32 b] from L2, duplicated ----
        {
            int unit = t >> 1;
            int q    = (t & 1) * 4;   // float4 index within unit's 8
            const float4* src = (const float4*)&g_h[p][unit][batch0];
            float* dst = hs + unit * 64;
            #pragma unroll
            for (int i = 0; i < 4; i++) {
                float4 v = __ldcg(&src[q + i]);
                float4 lo = make_float4(v.x, v.x, v.y, v.y);
                float4 hi = make_float4(v.z, v.z, v.w, v.w);
                *(float4*)&dst[(q + i) * 8]     = lo;
                *(float4*)&dst[(q + i) * 8 + 4] = hi;
            }
        }
        // ---- Stage x chunk every 64 steps ----
        if ((step & 63) == 0) {
            int bx = t >> 4, i = t & 15;
            float4 v = __ldg((const float4*)&x[(batch0 + bx) * TT + step] + i);
            float* d = xs + bx * 65 + i * 4;
            d[0] = v.x; d[1] = v.y; d[2] = v.z; d[3] = v.w;
        }
        __syncthreads();

        // ---- Gates: acc[g] = f32x2 over my 2 units ----
        float xv = xs[b * 65 + (step & 63)];
        u64 acc0 = pack2(fmaf(xv, wihr[0][0], biasr[0][0]),
                         fmaf(xv, wihr[0][1], biasr[0][1]));
        u64 acc1 = pack2(fmaf(xv, wihr[1][0], biasr[1][0]),
                         fmaf(xv, wihr[1][1], biasr[1][1]));
        u64 acc2 = pack2(fmaf(xv, wihr[2][0], biasr[2][0]),
                         fmaf(xv, wihr[2][1], biasr[2][1]));
        u64 acc3 = pack2(fmaf(xv, wihr[3][0], biasr[3][0]),
                         fmaf(xv, wihr[3][1], biasr[3][1]));

        const float* wp = Ws + up * 8;
        const float* hp = hs + b * 2;
        #pragma unroll 4
        for (int k = 0; k < HH; k++) {
            ulonglong2 wA = *(const ulonglong2*)(wp);      // gates 0,1
            ulonglong2 wB = *(const ulonglong2*)(wp + 4);  // gates 2,3
            u64 h2 = *(const u64*)hp;                      // (h,h) dup
            wp += 128; hp += 64;
            ffma2(acc0, wA.x, h2);
            ffma2(acc1, wA.y, h2);
            ffma2(acc2, wB.x, h2);
            ffma2(acc3, wB.y, h2);
        }

        float gi0, gi1, gf0, gf1, gg0, gg1, go0, go1;
        unpack2(acc0, gi0, gi1);  unpack2(acc1, gf0, gf1);
        unpack2(acc2, gg0, gg1);  unpack2(acc3, go0, go1);

        float i0 = sigm(gi0), f0 = sigm(gf0), G0 = tanhe(gg0), o0 = sigm(go0);
        c0 = f0 * c0 + i0 * G0;
        float h0 = o0 * tanhe(c0);
        float i1 = sigm(gi1), f1 = sigm(gf1), G1 = tanhe(gg1), o1 = sigm(go1);
        c1 = f1 * c1 + i1 * G1;
        float h1 = o1 * tanhe(c1);

        __stcg(&g_h[p ^ 1][unit0 + 2 * up + 0][batch0 + b], h0);
        __stcg(&g_h[p ^ 1][unit0 + 2 * up + 1][batch0 + b], h1);

        cluster_arrive_rel();   // release: h stores visible to peers
        cluster_wait_acq();     // acquire; also the intra-CTA barrier
        p ^= 1;
    }

    // ---- FC head: out[b] = sum_u relu(h[b,u]) * wfc[u] + bfc ----
    if (rank == 0) {
        int b_l = t & 31, seg = t >> 5;   // 16 segments x 16 units
        float s = 0.f;
        #pragma unroll
        for (int j = 0; j < 16; j++) {
            int uu = seg * 16 + j;
            float hval = __ldcg(&g_h[p][uu][batch0 + b_l]);
            s = fmaf(fmaxf(hval, 0.f), __ldg(&wfc[uu]), s);
        }
        float* red = smem;   // Ws region no longer needed
        __syncthreads();
        red[seg * 32 + b_l] = s;
        __syncthreads();
        if (t < 32) {
            float tot = __ldg(bfc);
            #pragma unroll
            for (int sg = 0; sg < 16; sg++) tot += red[sg * 32 + t];
            out[batch0 + t] = tot;
        }
    }
}

extern "C" void kernel_launch(void* const* d_in, const int* in_sizes, int n_in,
                              void* d_out, int out_size) {
    const float* x   = (const float*)d_in[0];
    const float* wih = (const float*)d_in[1];
    const float* whh = (const float*)d_in[2];
    const float* bih = (const float*)d_in[3];
    const float* bhh = (const float*)d_in[4];
    const float* wfc = (const float*)d_in[5];
    const float* bfc = (const float*)d_in[6];
    (void)in_sizes; (void)n_in; (void)out_size;

    size_t shmem = (size_t)(WS_FLOATS + HS_FLOATS + XS_FLOATS) * sizeof(float);
    cudaFuncSetAttribute(lstm_kernel,
                         cudaFuncAttributeMaxDynamicSharedMemorySize, (int)shmem);
    lstm_kernel<<<NCTA, NTHREADS, shmem>>>(x, wih, whh, bih, bhh, wfc, bfc,
                                           (float*)d_out);
}

// round 4
// speedup vs baseline: 1.4554x; 1.4554x over previous
#include <cuda_runtime.h>

// BG_LSTM: B=512, T=512, H=256, input size 1.
// 16 clusters x 8 CTAs; cluster owns 32 batches, CTA rank owns 32 units.
// W_hh slice SMEM-resident as f32x2 unit-pairs. h tile duplicated in SMEM
// ((h,h) pairs) so FFMA2 needs no splats. Thread tile: 2 units x 2 batches
// x half of k (k split across thread pairs, SMEM reduction). 512 thr/CTA.
// One release/acquire cluster barrier per step; h exchanged through L2.

#define TT 512
#define HH 256
#define CLUSTER 8
#define NCTA 128
#define NTHREADS 512
#define UPC 32
#define BPT 32
#define HS_STRIDE 68     // dup-h row stride (floats); 272B, 16B-aligned

__device__ float g_h[2][HH][512];   // [buf][unit][batch]

typedef unsigned long long u64;

__device__ __forceinline__ u64 pack2(float a, float b) {
    u64 r;
    asm("mov.b64 %0, {%1, %2};" : "=l"(r)
        : "r"(__float_as_uint(a)), "r"(__float_as_uint(b)));
    return r;
}
__device__ __forceinline__ void unpack2(u64 v, float &a, float &b) {
    unsigned int lo, hi;
    asm("mov.b64 {%0, %1}, %2;" : "=r"(lo), "=r"(hi) : "l"(v));
    a = __uint_as_float(lo); b = __uint_as_float(hi);
}
__device__ __forceinline__ void ffma2(u64 &acc, u64 a, u64 b) {
    asm("fma.rn.f32x2 %0, %1, %2, %3;" : "=l"(acc) : "l"(a), "l"(b), "l"(acc));
}
__device__ __forceinline__ u64 add2(u64 a, u64 b) {
    u64 r; asm("add.rn.f32x2 %0, %1, %2;" : "=l"(r) : "l"(a), "l"(b));
    return r;
}
__device__ __forceinline__ void cluster_arrive_rel() {
    asm volatile("barrier.cluster.arrive.release.aligned;" ::: "memory");
}
__device__ __forceinline__ void cluster_wait_acq() {
    asm volatile("barrier.cluster.wait.acquire.aligned;" ::: "memory");
}
__device__ __forceinline__ float tanh_a(float x) {
    float y; asm("tanh.approx.f32 %0, %1;" : "=f"(y) : "f"(x)); return y;
}
__device__ __forceinline__ float sigm(float x) {
    return fmaf(0.5f, tanh_a(0.5f * x), 0.5f);
}

#define WS_FLOATS (HH * 128)            // 32768
#define HS_FLOATS (HH * HS_STRIDE)      // 17408
#define XS_FLOATS (32 * 65)             // 2080
extern __shared__ __align__(16) float smem[];

__global__ void __cluster_dims__(CLUSTER, 1, 1) __launch_bounds__(NTHREADS, 1)
lstm_kernel(const float* __restrict__ x,    const float* __restrict__ wih,
            const float* __restrict__ whh,  const float* __restrict__ bih,
            const float* __restrict__ bhh,  const float* __restrict__ wfc,
            const float* __restrict__ bfc,  float* __restrict__ out)
{
    float* Ws = smem;                          // [k][up*8 + g*2 + j]
    float* hs = smem + WS_FLOATS;              // [k][b dup], stride 68
    float* xs = smem + WS_FLOATS + HS_FLOATS;  // [b][65]
    u64*  red = (u64*)hs;                      // reduction scratch (reused)

    const int t      = threadIdx.x;
    const int cta    = blockIdx.x;
    const int rank   = cta & (CLUSTER - 1);
    const int cl     = cta / CLUSTER;
    const int batch0 = cl * BPT;
    const int unit0  = rank * UPC;
    const int bp     = t & 15;          // batch pair: batches 2bp, 2bp+1
    const int up     = (t >> 4) & 15;   // unit pair:  units 2up, 2up+1
    const int kh     = t >> 8;          // k half (warps 0-7: kh=0)
    const int rr     = t & 255;         // reduction partner index

    // ---- Stage W_hh slice: Ws[k*128 + up*8 + g*2 + (uu&1)] ----
    {
        const float4* w4 = (const float4*)whh;
        #pragma unroll
        for (int j = 0; j < 16; j++) {
            int idx   = t + j * NTHREADS;   // 8192 float4 granules
            int row_l = idx >> 6;           // uu*4 + g
            int k4    = idx & 63;
            int uu = row_l >> 2, g = row_l & 3;
            float4 w = __ldg(&w4[(g * HH + unit0 + uu) * (HH / 4) + k4]);
            int col = (uu >> 1) * 8 + g * 2 + (uu & 1);
            Ws[(k4 * 4 + 0) * 128 + col] = w.x;
            Ws[(k4 * 4 + 1) * 128 + col] = w.y;
            Ws[(k4 * 4 + 2) * 128 + col] = w.z;
            Ws[(k4 * 4 + 3) * 128 + col] = w.w;
        }
    }

    // ---- Per-thread gate params for my 2 units ----
    float wihr[4][2], biasr[4][2];
    #pragma unroll
    for (int g = 0; g < 4; g++)
        #pragma unroll
        for (int j = 0; j < 2; j++) {
            int r = g * HH + unit0 + 2 * up + j;
            wihr[g][j]  = __ldg(&wih[r]);
            biasr[g][j] = __ldg(&bih[r]) + __ldg(&bhh[r]);
        }

    // ---- Zero my slice of g_h[0] ----
    if (t < 256) {
        float4 z = make_float4(0.f, 0.f, 0.f, 0.f);
        __stcg((float4*)&g_h[0][unit0 + (t >> 3)][batch0 + (t & 7) * 4], z);
    }
    float c00 = 0.f, c01 = 0.f, c10 = 0.f, c11 = 0.f;  // c[u][b]

    __syncthreads();
    cluster_arrive_rel();
    cluster_wait_acq();

    int p = 0;
    for (int step = 0; step < TT; step++) {
        // ---- Stage h tile from L2, duplicated: hs[unit*68 + 2b+{0,1}] ----
        {
            int unit = t >> 1, half = t & 1;
            const float4* src = (const float4*)&g_h[p][unit][batch0];
            float* dst = hs + unit * HS_STRIDE;
            #pragma unroll
            for (int i = 0; i < 4; i++) {
                int q = half * 4 + i;
                float4 v = __ldcg(&src[q]);
                *(float4*)&dst[q * 8]     = make_float4(v.x, v.x, v.y, v.y);
                *(float4*)&dst[q * 8 + 4] = make_float4(v.z, v.z, v.w, v.w);
            }
        }
        // ---- Stage x chunk every 64 steps ----
        if ((step & 63) == 0) {
            int bx = t >> 4, i = t & 15;
            float4 v = __ldg((const float4*)&x[(batch0 + bx) * TT + step] + i);
            float* d = xs + bx * 65 + i * 4;
            d[0] = v.x; d[1] = v.y; d[2] = v.z; d[3] = v.w;
        }
        __syncthreads();

        // ---- Accumulators acc[g][db]: f32x2 over my 2 units ----
        u64 acc[4][2];
        if (kh == 0) {
            float xv0 = xs[(2 * bp + 0) * 65 + (step & 63)];
            float xv1 = xs[(2 * bp + 1) * 65 + (step & 63)];
            #pragma unroll
            for (int g = 0; g < 4; g++) {
                acc[g][0] = pack2(fmaf(xv0, wihr[g][0], biasr[g][0]),
                                  fmaf(xv0, wihr[g][1], biasr[g][1]));
                acc[g][1] = pack2(fmaf(xv1, wihr[g][0], biasr[g][0]),
                                  fmaf(xv1, wihr[g][1], biasr[g][1]));
            }
        } else {
            #pragma unroll
            for (int g = 0; g < 4; g++) { acc[g][0] = 0ull; acc[g][1] = 0ull; }
        }

        // ---- Main dot: my half of k ----
        const float* wp = Ws + kh * 128 * 128 + up * 8;
        const float* hp = hs + kh * 128 * HS_STRIDE + bp * 4;
        #pragma unroll 8
        for (int k = 0; k < 128; k++) {
            ulonglong2 wA = *(const ulonglong2*)(wp);      // gates 0,1
            ulonglong2 wB = *(const ulonglong2*)(wp + 4);  // gates 2,3
            ulonglong2 hh = *(const ulonglong2*)(hp);      // (h0,h0),(h1,h1)
            wp += 128; hp += HS_STRIDE;
            ffma2(acc[0][0], wA.x, hh.x);  ffma2(acc[0][1], wA.x, hh.y);
            ffma2(acc[1][0], wA.y, hh.x);  ffma2(acc[1][1], wA.y, hh.y);
            ffma2(acc[2][0], wB.x, hh.x);  ffma2(acc[2][1], wB.x, hh.y);
            ffma2(acc[3][0], wB.y, hh.x);  ffma2(acc[3][1], wB.y, hh.y);
        }

        // ---- Cross-half reduction through SMEM (reuses hs region) ----
        __syncthreads();                       // hs reads done
        if (kh == 1) {
            #pragma unroll
            for (int g = 0; g < 4; g++) {
                red[(g * 2 + 0) * 256 + rr] = acc[g][0];
                red[(g * 2 + 1) * 256 + rr] = acc[g][1];
            }
        }
        __syncthreads();

        if (kh == 0) {
            #pragma unroll
            for (int g = 0; g < 4; g++) {
                acc[g][0] = add2(acc[g][0], red[(g * 2 + 0) * 256 + rr]);
                acc[g][1] = add2(acc[g][1], red[(g * 2 + 1) * 256 + rr]);
            }
            float gi0, gi1, gf0, gf1, gg0, gg1, go0, go1;
            float h00, h01, h10, h11;
            // batch 0 of pair
            unpack2(acc[0][0], gi0, gi1);  unpack2(acc[1][0], gf0, gf1);
            unpack2(acc[2][0], gg0, gg1);  unpack2(acc[3][0], go0, go1);
            c00 = sigm(gf0) * c00 + sigm(gi0) * tanh_a(gg0);
            h00 = sigm(go0) * tanh_a(c00);
            c10 = sigm(gf1) * c10 + sigm(gi1) * tanh_a(gg1);
            h10 = sigm(go1) * tanh_a(c10);
            // batch 1 of pair
            unpack2(acc[0][1], gi0, gi1);  unpack2(acc[1][1], gf0, gf1);
            unpack2(acc[2][1], gg0, gg1);  unpack2(acc[3][1], go0, go1);
            c01 = sigm(gf0) * c01 + sigm(gi0) * tanh_a(gg0);
            h01 = sigm(go0) * tanh_a(c01);
            c11 = sigm(gf1) * c11 + sigm(gi1) * tanh_a(gg1);
            h11 = sigm(go1) * tanh_a(c11);

            // store h: unit-major, batch-adjacent pairs -> STG.64
            float2 v0 = make_float2(h00, h01);
            float2 v1 = make_float2(h10, h11);
            __stcg((float2*)&g_h[p ^ 1][unit0 + 2 * up + 0][batch0 + 2 * bp], v0);
            __stcg((float2*)&g_h[p ^ 1][unit0 + 2 * up + 1][batch0 + 2 * bp], v1);
        }

        cluster_arrive_rel();
        cluster_wait_acq();
        p ^= 1;
    }

    // ---- FC head: out[b] = sum_u relu(h[b,u]) * wfc[u] + bfc ----
    if (rank == 0) {
        int b_l = t & 31, seg = t >> 5;   // 16 segments x 16 units
        float s = 0.f;
        #pragma unroll
        for (int j = 0; j < 16; j++) {
            int uu = seg * 16 + j;
            float hval = __ldcg(&g_h[p][uu][batch0 + b_l]);
            s = fmaf(fmaxf(hval, 0.f), __ldg(&wfc[uu]), s);
        }
        float* redf = smem;   // Ws region no longer needed
        __syncthreads();
        redf[seg * 32 + b_l] = s;
        __syncthreads();
        if (t < 32) {
            float tot = __ldg(bfc);
            #pragma unroll
            for (int sg = 0; sg < 16; sg++) tot += redf[sg * 32 + t];
            out[batch0 + t] = tot;
        }
    }
}

extern "C" void kernel_launch(void* const* d_in, const int* in_sizes, int n_in,
                              void* d_out, int out_size) {
    const float* x   = (const float*)d_in[0];
    const float* wih = (const float*)d_in[1];
    const float* whh = (const float*)d_in[2];
    const float* bih = (const float*)d_in[3];
    const float* bhh = (const float*)d_in[4];
    const float* wfc = (const float*)d_in[5];
    const float* bfc = (const float*)d_in[6];
    (void)in_sizes; (void)n_in; (void)out_size;

    size_t shmem = (size_t)(WS_FLOATS + HS_FLOATS + XS_FLOATS) * sizeof(float);
    cudaFuncSetAttribute(lstm_kernel,
                         cudaFuncAttributeMaxDynamicSharedMemorySize, (int)shmem);
    lstm_kernel<<<NCTA, NTHREADS, shmem>>>(x, wih, whh, bih, bhh, wfc, bfc,
                                           (float*)d_out);
}

// round 7
// speedup vs baseline: 4.0395x; 2.7756x over previous
#include <cuda_runtime.h>
#include <cuda_bf16.h>
#include <cstdint>

// BG_LSTM via warp-level HMMA (mma.sync bf16): B=512, T=512, H=256, in=1.
// 16 clusters x 8 CTAs. Cluster owns 32 batches; CTA rank owns 32 units
// (M=128 gate rows, m = u*4+g). W_hh in SMEM as two bf16 planes (hi, lo);
// h exchanged through L2 as packed (hi,lo) bf16 and staged into SMEM B
// planes each step. Gates = Whi*hhi + Wlo*hhi + Whi*hlo (fp32 accum in
// registers). Per step: stage B -> 192 HMMA/warp -> D to SMEM ->
// activations -> packed h store -> cluster barrier.

#define TT 512
#define CLUSTER 8
#define NCTA 128
#define NTHREADS 256
#define ASTR 264          // bf16 stride of A/B plane rows (528 B)

// Packed h: (hi_bf16 << 16) | lo_bf16, [buf][cluster][batch][unit]
__device__ uint32_t g_hbuf[2][16][32][256];

// ---- SMEM layout (byte offsets from aligned base) ----
#define OFF_AHI 0
#define OFF_ALO 67584              // 128*264*2
#define OFF_BHI 135168
#define OFF_BLO 152064             // + 32*264*2
#define OFF_GS  168960             // gates scratch: 32 x 132 fp32
#define OFF_XS  185856             // x chunk: 64 steps x 32 b fp32
#define SM_BYTES (194048 + 1024)

extern __shared__ __align__(16) char smem_raw[];

// ---------------- asm helpers ----------------
static __device__ __forceinline__ uint32_t smem_u32(const void* p) {
    uint32_t a;
    asm("{ .reg .u64 t; cvta.to.shared.u64 t, %1; cvt.u32.u64 %0, t; }"
        : "=r"(a) : "l"(p));
    return a;
}
static __device__ __forceinline__ uint32_t prmt(uint32_t a, uint32_t b, uint32_t s) {
    uint32_t r; asm("prmt.b32 %0,%1,%2,%3;" : "=r"(r) : "r"(a), "r"(b), "r"(s));
    return r;
}
static __device__ __forceinline__ void sts64(uint32_t a, uint32_t x, uint32_t y) {
    asm volatile("st.shared.v2.u32 [%0], {%1,%2};" :: "r"(a), "r"(x), "r"(y));
}
static __device__ __forceinline__ void sts32f(uint32_t a, float v) {
    asm volatile("st.shared.f32 [%0], %1;" :: "r"(a), "f"(v));
}
static __device__ __forceinline__ void sts32u(uint32_t a, uint32_t v) {
    asm volatile("st.shared.b32 [%0], %1;" :: "r"(a), "r"(v));
}
static __device__ __forceinline__ float lds32f(uint32_t a) {
    float v; asm volatile("ld.shared.f32 %0, [%1];" : "=f"(v) : "r"(a));
    return v;
}
static __device__ __forceinline__ float4 lds128f(uint32_t a) {
    float4 v;
    asm volatile("ld.shared.v4.f32 {%0,%1,%2,%3}, [%4];"
                 : "=f"(v.x), "=f"(v.y), "=f"(v.z), "=f"(v.w) : "r"(a));
    return v;
}
static __device__ __forceinline__ void ldsm4(uint32_t* r, uint32_t a) {
    asm volatile("ldmatrix.sync.aligned.m8n8.x4.shared.b16 {%0,%1,%2,%3}, [%4];"
                 : "=r"(r[0]), "=r"(r[1]), "=r"(r[2]), "=r"(r[3]) : "r"(a));
}
static __device__ __forceinline__ void mma16816(float* c, const uint32_t* a,
                                                const uint32_t* b) {
    asm volatile(
        "mma.sync.aligned.m16n8k16.row.col.f32.bf16.bf16.f32 "
        "{%0,%1,%2,%3},{%4,%5,%6,%7},{%8,%9},{%0,%1,%2,%3};"
        : "+f"(c[0]), "+f"(c[1]), "+f"(c[2]), "+f"(c[3])
        : "r"(a[0]), "r"(a[1]), "r"(a[2]), "r"(a[3]), "r"(b[0]), "r"(b[1]));
}
static __device__ __forceinline__ void cluster_arrive_rel() {
    asm volatile("barrier.cluster.arrive.release.aligned;" ::: "memory");
}
static __device__ __forceinline__ void cluster_wait_acq() {
    asm volatile("barrier.cluster.wait.acquire.aligned;" ::: "memory");
}
static __device__ __forceinline__ float tanh_a(float x) {
    float y; asm("tanh.approx.f32 %0, %1;" : "=f"(y) : "f"(x)); return y;
}
static __device__ __forceinline__ float sigm(float x) {
    return fmaf(0.5f, tanh_a(0.5f * x), 0.5f);
}
static __device__ __forceinline__ uint32_t pack_bf16x2(float hi_f, float lo_f) {
    __nv_bfloat16 h = __float2bfloat16(hi_f);
    __nv_bfloat16 l = __float2bfloat16(lo_f);
    return ((uint32_t)__bfloat16_as_ushort(h) << 16) |
           (uint32_t)__bfloat16_as_ushort(l);
}

__global__ void __cluster_dims__(CLUSTER, 1, 1) __launch_bounds__(NTHREADS, 1)
lstm_kernel(const float* __restrict__ x,    const float* __restrict__ wih,
            const float* __restrict__ whh,  const float* __restrict__ bih,
            const float* __restrict__ bhh,  const float* __restrict__ wfc,
            const float* __restrict__ bfc,  float* __restrict__ out)
{
    const int t      = threadIdx.x;
    const int lane   = t & 31;
    const int w      = t >> 5;          // warp 0..7
    const int cta    = blockIdx.x;
    const int rank   = cta & (CLUSTER - 1);
    const int cl     = cta >> 3;
    const int batch0 = cl * 32;
    const int unit0  = rank * 32;

    const uint32_t base = (smem_u32(smem_raw) + 1023u) & ~1023u;
    const uint32_t sAhi = base + OFF_AHI;
    const uint32_t sAlo = base + OFF_ALO;
    const uint32_t sBhi = base + OFF_BHI;
    const uint32_t sBlo = base + OFF_BLO;
    const uint32_t sGS  = base + OFF_GS;
    const uint32_t sXS  = base + OFF_XS;

    // ---- One-time: W' -> SMEM planes. Row m = u*4+g (u local). ----
    if (t < 128) {
        const int m = t;
        const float* wrow = whh + ((size_t)((m & 3) * 256 + unit0 + (m >> 2))) * 256;
        uint32_t ah = sAhi + (uint32_t)(m * ASTR * 2);
        uint32_t al = sAlo + (uint32_t)(m * ASTR * 2);
        #pragma unroll 8
        for (int k2 = 0; k2 < 128; k2++) {
            float2 wv = *(const float2*)(wrow + 2 * k2);
            __nv_bfloat16 hx = __float2bfloat16(wv.x);
            __nv_bfloat16 hy = __float2bfloat16(wv.y);
            float rx = wv.x - __bfloat162float(hx);
            float ry = wv.y - __bfloat162float(hy);
            uint32_t hi = ((uint32_t)__bfloat16_as_ushort(hy) << 16) |
                          (uint32_t)__bfloat16_as_ushort(hx);
            __nv_bfloat16 lx = __float2bfloat16(rx);
            __nv_bfloat16 ly = __float2bfloat16(ry);
            uint32_t lo = ((uint32_t)__bfloat16_as_ushort(ly) << 16) |
                          (uint32_t)__bfloat16_as_ushort(lx);
            sts32u(ah + 4u * k2, hi);
            sts32u(al + 4u * k2, lo);
        }
    }

    // ---- Per-thread activation params: unit u = t>>3, batches 4(t&7)+j ----
    const int u  = t >> 3;
    const int bq = t & 7;
    float wihr[4], biasr[4];
    #pragma unroll
    for (int g = 0; g < 4; g++) {
        int r = g * 256 + unit0 + u;
        wihr[g]  = __ldg(&wih[r]);
        biasr[g] = __ldg(&bih[r]) + __ldg(&bhh[r]);
    }

    // ---- Zero h buffer 0 for my cluster (1/8 per CTA) ----
    {
        uint32_t* gz = &g_hbuf[0][cl][0][0];
        #pragma unroll
        for (int i = 0; i < 4; i++)
            __stcg(&gz[rank * 1024 + t + i * 256], 0u);
    }
    float cc[4] = {0.f, 0.f, 0.f, 0.f};

    // ---- ldmatrix lane base addresses ----
    // A: rows 16w + (lane&15), col halves by lane>>4
    const uint32_t aOff =
        (uint32_t)(((16 * w + (lane & 15)) * ASTR + ((lane >> 4) * 8)) * 2);
    // B x4 pair P covers ntiles {2P, 2P+1}: n = 16P + (lane&7) + ((lane>>4)&1)*8,
    // k half by lane bit3.
    uint32_t bOff[2];
    #pragma unroll
    for (int P = 0; P < 2; P++) {
        int nB = 16 * P + (lane & 7) + (((lane >> 4) & 1) << 3);
        int ka = (lane & 8) ? 8 : 0;
        bOff[P] = (uint32_t)((nB * ASTR + ka) * 2);
    }

    __syncthreads();
    cluster_arrive_rel();
    cluster_wait_acq();

    int p = 0;
    for (int step = 0; step < TT; step++) {
        // ---- Stage B planes: unpack packed h -> hhi/hlo [n=b][k=u] ----
        #pragma unroll
        for (int i = 0; i < 8; i++) {
            int id = t + i * 256;           // 2048 granules: (b, 4-unit chunk)
            int b  = id >> 6;
            int uc = id & 63;
            uint4 v = __ldcg((const uint4*)&g_hbuf[p][cl][b][uc * 4]);
            uint32_t hiA = prmt(v.x, v.y, 0x7632u);
            uint32_t hiB = prmt(v.z, v.w, 0x7632u);
            uint32_t loA = prmt(v.x, v.y, 0x5410u);
            uint32_t loB = prmt(v.z, v.w, 0x5410u);
            uint32_t o = (uint32_t)(b * ASTR * 2 + uc * 8);
            sts64(sBhi + o, hiA, hiB);
            sts64(sBlo + o, loA, loB);
        }
        // ---- Stage x chunk every 64 steps: xs[(s&63)*32 + b] ----
        if ((step & 63) == 0) {
            #pragma unroll
            for (int i = 0; i < 2; i++) {
                int g  = t + i * 256;       // 512 float4 granules
                int bx = g >> 4, i4 = g & 15;
                float4 v = __ldg((const float4*)&x[(size_t)(batch0 + bx) * TT + step] + i4);
                uint32_t a0 = sXS + (uint32_t)(((i4 * 4 + 0) * 32 + bx) * 4);
                sts32f(a0,        v.x);
                sts32f(a0 + 128u, v.y);
                sts32f(a0 + 256u, v.z);
                sts32f(a0 + 384u, v.w);
            }
        }
        __syncthreads();

        // ---- MMA phase: c[nt][4] fp32, 3-term split over 16 k-tiles ----
        float c0[4] = {0,0,0,0}, c1[4] = {0,0,0,0};
        float c2[4] = {0,0,0,0}, c3[4] = {0,0,0,0};
        uint32_t aHi = sAhi + aOff, aLo = sAlo + aOff;
        uint32_t bh0 = sBhi + bOff[0], bh1 = sBhi + bOff[1];
        uint32_t bl0 = sBlo + bOff[0], bl1 = sBlo + bOff[1];
        #pragma unroll 4
        for (int kt = 0; kt < 16; kt++) {
            uint32_t ah[4], al[4], bh[8], bl[8];
            ldsm4(ah, aHi);  ldsm4(al, aLo);
            ldsm4(bh, bh0);  ldsm4(bh + 4, bh1);
            ldsm4(bl, bl0);  ldsm4(bl + 4, bl1);
            aHi += 32; aLo += 32; bh0 += 32; bh1 += 32; bl0 += 32; bl1 += 32;
            mma16816(c0, ah, bh);      mma16816(c1, ah, bh + 2);
            mma16816(c2, ah, bh + 4);  mma16816(c3, ah, bh + 6);
            mma16816(c0, al, bh);      mma16816(c1, al, bh + 2);
            mma16816(c2, al, bh + 4);  mma16816(c3, al, bh + 6);
            mma16816(c0, ah, bl);      mma16816(c1, ah, bl + 2);
            mma16816(c2, ah, bl + 4);  mma16816(c3, ah, bl + 6);
        }

        // ---- D fragments -> gates scratch gs[b][m] (m = u*4+g) ----
        {
            int m0 = 16 * w + (lane >> 2);
            int j0 = 2 * (lane & 3);
            float* cs[4] = {c0, c1, c2, c3};
            #pragma unroll
            for (int nt = 0; nt < 4; nt++) {
                int col = nt * 8 + j0;
                sts32f(sGS + (uint32_t)(((col    ) * 132 + m0    ) * 4), cs[nt][0]);
                sts32f(sGS + (uint32_t)(((col + 1) * 132 + m0    ) * 4), cs[nt][1]);
                sts32f(sGS + (uint32_t)(((col    ) * 132 + m0 + 8) * 4), cs[nt][2]);
                sts32f(sGS + (uint32_t)(((col + 1) * 132 + m0 + 8) * 4), cs[nt][3]);
            }
        }
        __syncthreads();

        // ---- Activations: 4 cells per thread (u, 4bq..4bq+3) ----
        #pragma unroll
        for (int j = 0; j < 4; j++) {
            int b = 4 * bq + j;
            float4 gv = lds128f(sGS + (uint32_t)((b * 132 + 4 * u) * 4));
            float xv  = lds32f(sXS + (uint32_t)(((step & 63) * 32 + b) * 4));
            float gi = gv.x + fmaf(xv, wihr[0], biasr[0]);
            float gf = gv.y + fmaf(xv, wihr[1], biasr[1]);
            float gg = gv.z + fmaf(xv, wihr[2], biasr[2]);
            float go = gv.w + fmaf(xv, wihr[3], biasr[3]);
            float c = sigm(gf) * cc[j] + sigm(gi) * tanh_a(gg);
            cc[j] = c;
            float hv = sigm(go) * tanh_a(c);
            __nv_bfloat16 hb = __float2bfloat16(hv);
            uint32_t pk = pack_bf16x2(hv, hv - __bfloat162float(hb));
            // pack_bf16x2(hi_part_src, residual) -- hi computed from hv
            __stcg(&g_hbuf[p ^ 1][cl][b][unit0 + u], pk);
        }

        cluster_arrive_rel();
        cluster_wait_acq();
        p ^= 1;
    }

    // ---- FC head (rank 0 CTA of each cluster) ----
    if (rank == 0) {
        int b = t >> 3, seg = t & 7;     // 8 segments x 32 units
        float s = 0.f;
        #pragma unroll 8
        for (int j = 0; j < 32; j++) {
            int uu = seg * 32 + j;
            uint32_t pk = __ldcg(&g_hbuf[p][cl][b][uu]);
            float h = __bfloat162float(__ushort_as_bfloat16((unsigned short)(pk >> 16))) +
                      __bfloat162float(__ushort_as_bfloat16((unsigned short)(pk & 0xFFFF)));
            s = fmaf(fmaxf(h, 0.f), __ldg(&wfc[uu]), s);
        }
        sts32f(sGS + (uint32_t)((b * 8 + seg) * 4), s);
        __syncthreads();
        if (t < 32) {
            float tot = __ldg(bfc);
            #pragma unroll
            for (int sg = 0; sg < 8; sg++)
                tot += lds32f(sGS + (uint32_t)((t * 8 + sg) * 4));
            out[batch0 + t] = tot;
        }
    }
}

extern "C" void kernel_launch(void* const* d_in, const int* in_sizes, int n_in,
                              void* d_out, int out_size) {
    const float* x   = (const float*)d_in[0];
    const float* wih = (const float*)d_in[1];
    const float* whh = (const float*)d_in[2];
    const float* bih = (const float*)d_in[3];
    const float* bhh = (const float*)d_in[4];
    const float* wfc = (const float*)d_in[5];
    const float* bfc = (const float*)d_in[6];
    (void)in_sizes; (void)n_in; (void)out_size;

    cudaFuncSetAttribute(lstm_kernel,
                         cudaFuncAttributeMaxDynamicSharedMemorySize, SM_BYTES);
    lstm_kernel<<<NCTA, NTHREADS, SM_BYTES>>>(x, wih, whh, bih, bhh, wfc, bfc,
                                              (float*)d_out);
}

// round 8
// speedup vs baseline: 4.5979x; 1.1382x over previous
#include <cuda_runtime.h>
#include <cuda_bf16.h>
#include <cstdint>

// BG_LSTM via warp-level HMMA: B=512, T=512, H=256, in=1.
// Templated on RANKS (CTAs per cluster). Cluster owns 32 batches; CTA rank
// owns UPC=256/RANKS units (M=4*UPC gate rows). W_hh in SMEM as bf16 hi/lo
// planes; h exchanged via L2 as packed (hi,lo) bf16; gates =
// Whi*hhi + Wlo*hhi + Whi*hlo, fp32 register accumulators.
// RANKS=16 -> 128 thr/CTA, ~112KB SMEM, 2 CTAs/SM co-resident (overlap the
// serialized step chain). Fallback RANKS=8 = proven R7 shape.

#define TT 512
#define ASTR 264          // bf16 row stride of A/B planes (528 B)

// Packed h: (hi_bf16 << 16) | lo_bf16, [buf][cluster][batch][unit]
__device__ uint32_t g_hbuf[2][16][32][256];

extern __shared__ __align__(16) char smem_raw[];

// ---------------- asm helpers ----------------
static __device__ __forceinline__ uint32_t smem_u32(const void* p) {
    uint32_t a;
    asm("{ .reg .u64 t; cvta.to.shared.u64 t, %1; cvt.u32.u64 %0, t; }"
        : "=r"(a) : "l"(p));
    return a;
}
static __device__ __forceinline__ uint32_t prmt(uint32_t a, uint32_t b, uint32_t s) {
    uint32_t r; asm("prmt.b32 %0,%1,%2,%3;" : "=r"(r) : "r"(a), "r"(b), "r"(s));
    return r;
}
static __device__ __forceinline__ void sts64(uint32_t a, uint32_t x, uint32_t y) {
    asm volatile("st.shared.v2.u32 [%0], {%1,%2};" :: "r"(a), "r"(x), "r"(y));
}
static __device__ __forceinline__ void sts32f(uint32_t a, float v) {
    asm volatile("st.shared.f32 [%0], %1;" :: "r"(a), "f"(v));
}
static __device__ __forceinline__ void sts32u(uint32_t a, uint32_t v) {
    asm volatile("st.shared.b32 [%0], %1;" :: "r"(a), "r"(v));
}
static __device__ __forceinline__ float lds32f(uint32_t a) {
    float v; asm volatile("ld.shared.f32 %0, [%1];" : "=f"(v) : "r"(a));
    return v;
}
static __device__ __forceinline__ float4 lds128f(uint32_t a) {
    float4 v;
    asm volatile("ld.shared.v4.f32 {%0,%1,%2,%3}, [%4];"
                 : "=f"(v.x), "=f"(v.y), "=f"(v.z), "=f"(v.w) : "r"(a));
    return v;
}
static __device__ __forceinline__ void ldsm4(uint32_t* r, uint32_t a) {
    asm volatile("ldmatrix.sync.aligned.m8n8.x4.shared.b16 {%0,%1,%2,%3}, [%4];"
                 : "=r"(r[0]), "=r"(r[1]), "=r"(r[2]), "=r"(r[3]) : "r"(a));
}
static __device__ __forceinline__ void mma16816(float* c, const uint32_t* a,
                                                const uint32_t* b) {
    asm volatile(
        "mma.sync.aligned.m16n8k16.row.col.f32.bf16.bf16.f32 "
        "{%0,%1,%2,%3},{%4,%5,%6,%7},{%8,%9},{%0,%1,%2,%3};"
        : "+f"(c[0]), "+f"(c[1]), "+f"(c[2]), "+f"(c[3])
        : "r"(a[0]), "r"(a[1]), "r"(a[2]), "r"(a[3]), "r"(b[0]), "r"(b[1]));
}
static __device__ __forceinline__ void cluster_arrive_rel() {
    asm volatile("barrier.cluster.arrive.release.aligned;" ::: "memory");
}
static __device__ __forceinline__ void cluster_wait_acq() {
    asm volatile("barrier.cluster.wait.acquire.aligned;" ::: "memory");
}
static __device__ __forceinline__ float tanh_a(float x) {
    float y; asm("tanh.approx.f32 %0, %1;" : "=f"(y) : "f"(x)); return y;
}
static __device__ __forceinline__ float sigm(float x) {
    return fmaf(0.5f, tanh_a(0.5f * x), 0.5f);
}
static __device__ __forceinline__ uint32_t pack_hilo(float v) {
    __nv_bfloat16 h = __float2bfloat16(v);
    __nv_bfloat16 l = __float2bfloat16(v - __bfloat162float(h));
    return ((uint32_t)__bfloat16_as_ushort(h) << 16) |
           (uint32_t)__bfloat16_as_ushort(l);
}

template <int RANKS>
__global__ void __launch_bounds__((256 / RANKS) * 8, 1)
lstm_kernel(const float* __restrict__ x,    const float* __restrict__ wih,
            const float* __restrict__ whh,  const float* __restrict__ bih,
            const float* __restrict__ bhh,  const float* __restrict__ wfc,
            const float* __restrict__ bfc,  float* __restrict__ out)
{
    constexpr int UPC    = 256 / RANKS;     // units per CTA
    constexpr int NT     = UPC * 8;         // threads
    constexpr int NWARPS = UPC / 4;
    constexpr int MROWS  = UPC * 4;
    constexpr uint32_t PLANE_A = MROWS * ASTR * 2;      // bytes
    constexpr uint32_t PLANE_B = 32 * ASTR * 2;         // 16896
    constexpr uint32_t OFF_ALO = PLANE_A;
    constexpr uint32_t OFF_BHI = 2 * PLANE_A;
    constexpr uint32_t OFF_BLO = 2 * PLANE_A + PLANE_B;
    constexpr uint32_t OFF_GS  = 2 * PLANE_A + 2 * PLANE_B;
    constexpr uint32_t GS_WARP = 2560;                  // 32 b x 20 floats
    constexpr uint32_t OFF_XS  = OFF_GS + NWARPS * GS_WARP;

    const int t      = threadIdx.x;
    const int lane   = t & 31;
    const int w      = t >> 5;
    const int cta    = blockIdx.x;
    const int rank   = cta % RANKS;
    const int cl     = cta / RANKS;
    const int batch0 = cl * 32;
    const int unit0  = rank * UPC;

    const uint32_t base = (smem_u32(smem_raw) + 1023u) & ~1023u;
    const uint32_t sAhi = base;
    const uint32_t sAlo = base + OFF_ALO;
    const uint32_t sBhi = base + OFF_BHI;
    const uint32_t sBlo = base + OFF_BLO;
    const uint32_t sGS  = base + OFF_GS;
    const uint32_t sXS  = base + OFF_XS;

    // ---- One-time: W' -> SMEM planes. Row m = u*4+g (u local). ----
    if (t < MROWS) {
        const int m = t;
        const float* wrow = whh + ((size_t)((m & 3) * 256 + unit0 + (m >> 2))) * 256;
        uint32_t ah = sAhi + (uint32_t)(m * ASTR * 2);
        uint32_t al = sAlo + (uint32_t)(m * ASTR * 2);
        #pragma unroll 8
        for (int k2 = 0; k2 < 128; k2++) {
            float2 wv = *(const float2*)(wrow + 2 * k2);
            __nv_bfloat16 hx = __float2bfloat16(wv.x);
            __nv_bfloat16 hy = __float2bfloat16(wv.y);
            float rx = wv.x - __bfloat162float(hx);
            float ry = wv.y - __bfloat162float(hy);
            uint32_t hi = ((uint32_t)__bfloat16_as_ushort(hy) << 16) |
                          (uint32_t)__bfloat16_as_ushort(hx);
            __nv_bfloat16 lx = __float2bfloat16(rx);
            __nv_bfloat16 ly = __float2bfloat16(ry);
            uint32_t lo = ((uint32_t)__bfloat16_as_ushort(ly) << 16) |
                          (uint32_t)__bfloat16_as_ushort(lx);
            sts32u(ah + 4u * k2, hi);
            sts32u(al + 4u * k2, lo);
        }
    }

    // ---- Per-thread activation params: unit u = t>>3 (local), b = 4(t&7)+j
    const int u  = t >> 3;
    const int bq = t & 7;
    float wihr[4], biasr[4];
    #pragma unroll
    for (int g = 0; g < 4; g++) {
        int r = g * 256 + unit0 + u;
        wihr[g]  = __ldg(&wih[r]);
        biasr[g] = __ldg(&bih[r]) + __ldg(&bhh[r]);
    }

    // ---- Zero h buffer 0 for my cluster (cooperative across ranks) ----
    {
        uint32_t* gz = &g_hbuf[0][cl][0][0];
        #pragma unroll
        for (int i = 0; i < 8192 / (RANKS * NT); i++)
            __stcg(&gz[rank * (8192 / RANKS) + t + i * NT], 0u);
    }
    float cc[4] = {0.f, 0.f, 0.f, 0.f};

    // ---- ldmatrix lane base addresses ----
    const uint32_t aOff =
        (uint32_t)(((16 * w + (lane & 15)) * ASTR + ((lane >> 4) * 8)) * 2);
    uint32_t bOff[2];
    #pragma unroll
    for (int P = 0; P < 2; P++) {
        int nB = 16 * P + (lane & 7) + (((lane >> 4) & 1) << 3);
        int ka = (lane & 8) ? 8 : 0;
        bOff[P] = (uint32_t)((nB * ASTR + ka) * 2);
    }

    __syncthreads();
    cluster_arrive_rel();
    cluster_wait_acq();

    int p = 0;
    for (int step = 0; step < TT; step++) {
        // ---- Stage B planes: unpack packed h -> hhi/hlo [n=b][k=u] ----
        #pragma unroll
        for (int i = 0; i < 2048 / NT; i++) {
            int id = t + i * NT;           // 2048 granules: (b, 4-unit chunk)
            int b  = id >> 6;
            int uc = id & 63;
            uint4 v = __ldcg((const uint4*)&g_hbuf[p][cl][b][uc * 4]);
            uint32_t hiA = prmt(v.x, v.y, 0x7632u);
            uint32_t hiB = prmt(v.z, v.w, 0x7632u);
            uint32_t loA = prmt(v.x, v.y, 0x5410u);
            uint32_t loB = prmt(v.z, v.w, 0x5410u);
            uint32_t o = (uint32_t)(b * ASTR * 2 + uc * 8);
            sts64(sBhi + o, hiA, hiB);
            sts64(sBlo + o, loA, loB);
        }
        // ---- Stage x chunk every 16 steps: xs[(s&15)*32 + b] ----
        if ((step & 15) == 0 && t < 128) {
            int bx = t >> 2, i4 = t & 3;
            float4 v = __ldg((const float4*)&x[(size_t)(batch0 + bx) * TT + step] + i4);
            uint32_t a0 = sXS + (uint32_t)(((i4 * 4 + 0) * 32 + bx) * 4);
            sts32f(a0,        v.x);
            sts32f(a0 + 128u, v.y);
            sts32f(a0 + 256u, v.z);
            sts32f(a0 + 384u, v.w);
        }
        __syncthreads();

        // ---- MMA phase: 3-term split over 16 k-tiles ----
        float c0[4] = {0,0,0,0}, c1[4] = {0,0,0,0};
        float c2[4] = {0,0,0,0}, c3[4] = {0,0,0,0};
        uint32_t aHi = sAhi + aOff, aLo = sAlo + aOff;
        uint32_t bh0 = sBhi + bOff[0], bh1 = sBhi + bOff[1];
        uint32_t bl0 = sBlo + bOff[0], bl1 = sBlo + bOff[1];
        #pragma unroll 4
        for (int kt = 0; kt < 16; kt++) {
            uint32_t ah[4], al[4], bh[8], bl[8];
            ldsm4(ah, aHi);  ldsm4(al, aLo);
            ldsm4(bh, bh0);  ldsm4(bh + 4, bh1);
            ldsm4(bl, bl0);  ldsm4(bl + 4, bl1);
            aHi += 32; aLo += 32; bh0 += 32; bh1 += 32; bl0 += 32; bl1 += 32;
            mma16816(c0, ah, bh);      mma16816(c1, ah, bh + 2);
            mma16816(c2, ah, bh + 4);  mma16816(c3, ah, bh + 6);
            mma16816(c0, al, bh);      mma16816(c1, al, bh + 2);
            mma16816(c2, al, bh + 4);  mma16816(c3, al, bh + 6);
            mma16816(c0, ah, bl);      mma16816(c1, ah, bl + 2);
            mma16816(c2, ah, bl + 4);  mma16816(c3, ah, bl + 6);
        }

        // ---- D fragments -> warp-private gates scratch gs[b][m_local] ----
        {
            uint32_t gw = sGS + (uint32_t)(w * GS_WARP);
            int mr = lane >> 2;            // m_local rows mr, mr+8
            int j0 = 2 * (lane & 3);
            float* cs[4] = {c0, c1, c2, c3};
            #pragma unroll
            for (int nt = 0; nt < 4; nt++) {
                int col = nt * 8 + j0;
                sts32f(gw + (uint32_t)((col    ) * 80 + mr * 4),       cs[nt][0]);
                sts32f(gw + (uint32_t)((col + 1) * 80 + mr * 4),       cs[nt][1]);
                sts32f(gw + (uint32_t)((col    ) * 80 + (mr + 8) * 4), cs[nt][2]);
                sts32f(gw + (uint32_t)((col + 1) * 80 + (mr + 8) * 4), cs[nt][3]);
            }
        }
        __syncwarp();

        // ---- Activations (warp-local): 4 cells (u, 4bq+j) ----
        {
            uint32_t gw = sGS + (uint32_t)(w * GS_WARP) + (uint32_t)((lane >> 3) * 16);
            #pragma unroll
            for (int j = 0; j < 4; j++) {
                int b = 4 * bq + j;
                float4 gv = lds128f(gw + (uint32_t)(b * 80));
                float xv  = lds32f(sXS + (uint32_t)(((step & 15) * 32 + b) * 4));
                float gi = gv.x + fmaf(xv, wihr[0], biasr[0]);
                float gf = gv.y + fmaf(xv, wihr[1], biasr[1]);
                float gg = gv.z + fmaf(xv, wihr[2], biasr[2]);
                float go = gv.w + fmaf(xv, wihr[3], biasr[3]);
                float c = sigm(gf) * cc[j] + sigm(gi) * tanh_a(gg);
                cc[j] = c;
                float hv = sigm(go) * tanh_a(c);
                __stcg(&g_hbuf[p ^ 1][cl][b][unit0 + u], pack_hilo(hv));
            }
        }

        cluster_arrive_rel();
        cluster_wait_acq();
        p ^= 1;
    }

    // ---- FC head (rank 0 CTA of each cluster) ----
    if (rank == 0) {
        constexpr int SEGS = NT / 32;
        constexpr int UPS  = 256 / SEGS;
        int b = t / SEGS, seg = t % SEGS;
        float s = 0.f;
        #pragma unroll 8
        for (int j = 0; j < UPS; j++) {
            int uu = seg * UPS + j;
            uint32_t pk = __ldcg(&g_hbuf[p][cl][b][uu]);
            float h = __bfloat162float(__ushort_as_bfloat16((unsigned short)(pk >> 16))) +
                      __bfloat162float(__ushort_as_bfloat16((unsigned short)(pk & 0xFFFF)));
            s = fmaf(fmaxf(h, 0.f), __ldg(&wfc[uu]), s);
        }
        sts32f(sGS + (uint32_t)((b * SEGS + seg) * 4), s);
        __syncthreads();
        if (t < 32) {
            float tot = __ldg(bfc);
            #pragma unroll
            for (int sg = 0; sg < SEGS; sg++)
                tot += lds32f(sGS + (uint32_t)((t * SEGS + sg) * 4));
            out[batch0 + t] = tot;
        }
    }
}

static constexpr int smem_bytes(int ranks) {
    int upc = 256 / ranks;
    int planeA = upc * 4 * ASTR * 2;
    int planeB = 32 * ASTR * 2;
    int gs = (upc / 4) * 2560;
    return 2 * planeA + 2 * planeB + gs + 2048 + 1024;
}

extern "C" void kernel_launch(void* const* d_in, const int* in_sizes, int n_in,
                              void* d_out, int out_size) {
    const float* x   = (const float*)d_in[0];
    const float* wih = (const float*)d_in[1];
    const float* whh = (const float*)d_in[2];
    const float* bih = (const float*)d_in[3];
    const float* bhh = (const float*)d_in[4];
    const float* wfc = (const float*)d_in[5];
    const float* bfc = (const float*)d_in[6];
    (void)in_sizes; (void)n_in; (void)out_size;
    float* o = (float*)d_out;

    constexpr int SM16 = smem_bytes(16);   // ~114688 -> 2 CTAs/SM
    constexpr int SM8  = smem_bytes(8);    // ~192512 -> 1 CTA/SM

    cudaFuncSetAttribute(lstm_kernel<16>,
                         cudaFuncAttributeMaxDynamicSharedMemorySize, SM16);
    cudaFuncSetAttribute(lstm_kernel<16>,
                         cudaFuncAttributeNonPortableClusterSizeAllowed, 1);
    cudaFuncSetAttribute(lstm_kernel<8>,
                         cudaFuncAttributeMaxDynamicSharedMemorySize, SM8);

    // Probe whether a 16-CTA cluster is launchable for this config.
    cudaLaunchConfig_t probe = {};
    probe.gridDim  = {256, 1, 1};
    probe.blockDim = {128, 1, 1};
    probe.dynamicSmemBytes = SM16;
    int maxc = 0;
    cudaError_t qe = cudaOccupancyMaxPotentialClusterSize(
        &maxc, (void*)lstm_kernel<16>, &probe);

    if (qe == cudaSuccess && maxc >= 16) {
        cudaLaunchConfig_t cfg = {};
        cfg.gridDim  = {256, 1, 1};
        cfg.blockDim = {128, 1, 1};
        cfg.dynamicSmemBytes = SM16;
        cudaLaunchAttribute at[1];
        at[0].id = cudaLaunchAttributeClusterDimension;
        at[0].val.clusterDim = {16, 1, 1};
        cfg.attrs = at; cfg.numAttrs = 1;
        cudaLaunchKernelEx(&cfg, lstm_kernel<16>, x, wih, whh, bih, bhh,
                           wfc, bfc, o);
    } else {
        cudaLaunchConfig_t cfg = {};
        cfg.gridDim  = {128, 1, 1};
        cfg.blockDim = {256, 1, 1};
        cfg.dynamicSmemBytes = SM8;
        cudaLaunchAttribute at[1];
        at[0].id = cudaLaunchAttributeClusterDimension;
        at[0].val.clusterDim = {8, 1, 1};
        cfg.attrs = at; cfg.numAttrs = 1;
        cudaLaunchKernelEx(&cfg, lstm_kernel<8>, x, wih, whh, bih, bhh,
                           wfc, bfc, o);
    }
}